// round 13
// baseline (speedup 1.0000x reference)
#include <cuda_runtime.h>
#include <math.h>

#define BB 16
#define NPIX 245760          // 384*640
#define NPIX4 (NPIX/4)
#define N2  491520           // 2*NPIX
#define CAP 16384            // global candidate buffer per (batch,query)
#define LCAP 768             // per-block smem staging per query (gather)
#define NB0 4096             // L0 bins (12-bit prefix)
#define SUBCAP 2048          // sub-bin candidate list cap (tail select)

// ---------------- scratch (static device memory; no runtime allocs) ----------------
__device__ double g_sums[BB][5];                      // a00,a01,a11,b0,b1
__device__ int    g_cntm[BB];                         // masked gt count (= n)
__device__ int    g_cnt[BB];                          // static-pixel count
__device__ int    g_arrive[BB];                       // last-block counters (stats, then gather)
__device__ float  g_rr[BB];
__device__ float  g_loss[32];
__device__ float  g_qv[64];                           // per (b,q) quantile value
__device__ unsigned int g_pref[64], g_rem[64];        // per (b,q): 12-bit L0 prefix, residual rank
__device__ int    g_candcnt[64];
__device__ int    g_done;                             // trim last-block counter
__device__ unsigned int g_hist0[BB][NB0];
__device__ unsigned int g_hist1[64][256];             // 8-bit sub-hist, built in gather
__device__ unsigned int g_histt[32][2048];            // built in compact
__device__ unsigned int g_cand[64 * CAP];             // 4 MB
__device__ unsigned int g_keys[(size_t)BB * N2];      // compacted masked gt keys
__device__ unsigned int g_rd_keys[(size_t)BB * NPIX];
__device__ unsigned int g_ra_keys[(size_t)BB * NPIX];
__device__ float  g_dp [(size_t)BB * NPIX];
__device__ float  g_dgt[(size_t)BB * NPIX];
__device__ unsigned char g_m12[(size_t)BB * NPIX4];

// ---------------- helpers ----------------
__device__ __forceinline__ unsigned int fkey(float x) {
    unsigned int u = __float_as_uint(x);
    return (u & 0x80000000u) ? ~u : (u | 0x80000000u);
}
__device__ __forceinline__ float kinv(unsigned int k) {
    unsigned int u = (k & 0x80000000u) ? (k & 0x7fffffffu) : ~k;
    return __uint_as_float(u);
}
__device__ __forceinline__ float hubf(float v) {
    return (v <= 0.03f) ? (0.5f * (v * v)) / 0.03f : (v - 0.015f);
}

// Warp exclusive scan of per-thread count; returns (excl, warp_total).
__device__ __forceinline__ void warp_exscan(int tot, int lane, int* excl, int* wtot) {
    int v = tot;
#pragma unroll
    for (int o = 1; o < 32; o <<= 1) {
        int t = __shfl_up_sync(0xffffffffu, v, o);
        if (lane >= o) v += t;
    }
    *excl = v - tot;
    *wtot = __shfl_sync(0xffffffffu, v, 31);
}

// 256-thread block: exclusive scan of per-thread value s -> sP[0..256]. Ends synced.
__device__ __forceinline__ void scan256(unsigned s, unsigned* sP) {
    int tid = threadIdx.x, lane = tid & 31, wp = tid >> 5;
    unsigned v = s;
#pragma unroll
    for (int o = 1; o < 32; o <<= 1) {
        unsigned t = __shfl_up_sync(0xffffffffu, v, o);
        if (lane >= o) v += t;
    }
    __shared__ unsigned wtot[8];
    if (lane == 31) wtot[wp] = v;
    __syncthreads();
    unsigned wo = 0;
    for (int w = 0; w < wp; w++) wo += wtot[w];
    unsigned excl = wo + v - s;
    sP[tid] = excl;
    if (tid == 255) sP[256] = excl + s;
    __syncthreads();
}

__device__ __forceinline__ void block_exscan_chunks(const unsigned int* sh,
                                                    unsigned int* sP, int chunk) {
    int tid = threadIdx.x;
    unsigned s = 0;
#pragma unroll 4
    for (int j = 0; j < chunk; j++) s += sh[tid * chunk + j];
    scan256(s, sP);
}

__device__ __forceinline__ int bsearch256(const unsigned int* sP, unsigned rank) {
    int lo = 0, hi = 255;
    while (lo < hi) {
        int mid = (lo + hi + 1) >> 1;
        if (sP[mid] <= rank) lo = mid; else hi = mid - 1;
    }
    return lo;
}

__device__ __forceinline__ void resolve_one(const unsigned int* sh, const unsigned int* sP,
                                            int chunk, int nb, unsigned rank,
                                            unsigned* bin_out, unsigned* rem_out) {
    int lo = bsearch256(sP, rank);
    unsigned cum = sP[lo];
    int bin = lo * chunk;
    int end = bin + chunk;
    if (end > nb) end = nb;
    while (bin + 1 < end && cum + sh[bin] <= rank) { cum += sh[bin]; bin++; }
    *bin_out = (unsigned)bin;
    *rem_out = rank - cum;
}

__device__ __forceinline__ void ranks_for_n(int n, unsigned* r) {
    int nm1 = (n > 1) ? (n - 1) : 0;
    float pos05 = 0.05f * (float)nm1;
    float pos95 = 0.95f * (float)nm1;
    r[0] = (unsigned)floorf(pos05);
    r[1] = (unsigned)ceilf(pos05);
    r[2] = (unsigned)floorf(pos95);
    r[3] = (unsigned)ceilf(pos95);
}

// ---------------- kernels ----------------
// Pass 1: moments + compacted gt keys + smem hist L0 (12-bit) + dp/dgt/m12 precompute.
// Block-aggregated counter reservation. Last block per batch resolves L0 prefixes.
__global__ void k_stats(const float* __restrict__ pred, const float* __restrict__ gt,
                        const float* __restrict__ mask) {
    __shared__ unsigned int hh[NB0];
    __shared__ unsigned int sPP[257];
    __shared__ unsigned swt[8];      // per-warp totals
    __shared__ unsigned swoff[8];    // per-warp offsets
    __shared__ unsigned sbase;
    __shared__ int s_last;
    int b = blockIdx.y;
    int tid = threadIdx.x;
    for (int i = tid; i < NB0; i += blockDim.x) hh[i] = 0u;
    __syncthreads();
    const float4* p0 = (const float4*)(pred + (size_t)b * N2);
    const float4* p1 = (const float4*)(pred + (size_t)b * N2 + NPIX);
    const float4* g0 = (const float4*)(gt   + (size_t)b * N2);
    const float4* g1 = (const float4*)(gt   + (size_t)b * N2 + NPIX);
    const float4* m0 = (const float4*)(mask + (size_t)b * N2);
    const float4* m1 = (const float4*)(mask + (size_t)b * N2 + NPIX);
    float4* dp4  = (float4*)(g_dp  + (size_t)b * NPIX);
    float4* dg4  = (float4*)(g_dgt + (size_t)b * NPIX);
    unsigned char* mm = g_m12 + (size_t)b * NPIX4;
    unsigned int* keys = g_keys + (size_t)b * N2;
    float a00 = 0.f, a01 = 0.f, a11 = 0.f, bb0 = 0.f, bb1 = 0.f;
    int lane = tid & 31;
    int wp = tid >> 5;
    int tot_threads = gridDim.x * blockDim.x;
    for (int i = blockIdx.x * blockDim.x + tid; i < NPIX4; i += tot_threads) {
        float4 P0 = __ldcs(p0 + i), P1 = __ldcs(p1 + i);
        float4 G0 = __ldcs(g0 + i), G1 = __ldcs(g1 + i);
        float4 M0 = __ldcs(m0 + i), M1 = __ldcs(m1 + i);
        float4 dpv, dgv;
        unsigned kv[8];
        unsigned actbits = 0, mbyte = 0;
#define DO(c, idx, bit) { bool a0 = M0.c > 0.5f, a1 = M1.c > 0.5f; \
        if (a0) { a00 += P0.c * P0.c; a01 += P0.c; a11 += 1.f; bb0 += P0.c * G0.c; bb1 += G0.c; } \
        if (a1) { a00 += P1.c * P1.c; a01 += P1.c; a11 += 1.f; bb0 += P1.c * G1.c; bb1 += G1.c; } \
        if (a0) actbits |= (1u << idx); kv[idx] = fkey(G0.c); \
        if (a1) actbits |= (1u << (idx + 4)); kv[idx + 4] = fkey(G1.c); \
        if (a0 && a1) mbyte |= (1u << bit); \
        dpv.c = P1.c - P0.c; dgv.c = G1.c - G0.c; }
        DO(x, 0, 0) DO(y, 1, 1) DO(z, 2, 2) DO(w, 3, 3)
#undef DO
        int tot = __popc(actbits), excl, wtot;
        warp_exscan(tot, lane, &excl, &wtot);
        if (lane == 0) swt[wp] = (unsigned)wtot;
        __syncthreads();
        if (tid == 0) {
            unsigned acc = 0;
            for (int w = 0; w < 8; w++) { swoff[w] = acc; acc += swt[w]; }
            sbase = acc ? (unsigned)atomicAdd(&g_cntm[b], (int)acc) : 0u;
        }
        __syncthreads();
        unsigned pos = sbase + swoff[wp] + (unsigned)excl;
#pragma unroll
        for (int s = 0; s < 8; s++) {
            if (actbits & (1u << s)) {
                keys[pos] = kv[s];
                atomicAdd(&hh[kv[s] >> 20], 1u);
                pos++;
            }
        }
        dp4[i] = dpv; dg4[i] = dgv; mm[i] = (unsigned char)mbyte;
    }
    double d0 = a00, d1 = a01, d2 = a11, d3 = bb0, d4 = bb1;
    for (int off = 16; off > 0; off >>= 1) {
        d0 += __shfl_down_sync(0xffffffffu, d0, off);
        d1 += __shfl_down_sync(0xffffffffu, d1, off);
        d2 += __shfl_down_sync(0xffffffffu, d2, off);
        d3 += __shfl_down_sync(0xffffffffu, d3, off);
        d4 += __shfl_down_sync(0xffffffffu, d4, off);
    }
    __shared__ double shd[8][5];
    if (lane == 0) { shd[wp][0] = d0; shd[wp][1] = d1; shd[wp][2] = d2; shd[wp][3] = d3; shd[wp][4] = d4; }
    __syncthreads();
    if (tid == 0) {
        double s0 = 0, s1 = 0, s2 = 0, s3 = 0, s4 = 0;
        for (int w = 0; w < 8; w++) { s0 += shd[w][0]; s1 += shd[w][1]; s2 += shd[w][2]; s3 += shd[w][3]; s4 += shd[w][4]; }
        atomicAdd(&g_sums[b][0], s0); atomicAdd(&g_sums[b][1], s1);
        atomicAdd(&g_sums[b][2], s2); atomicAdd(&g_sums[b][3], s3);
        atomicAdd(&g_sums[b][4], s4);
    }
    unsigned int* gh = g_hist0[b];
    for (int i = tid; i < NB0; i += blockDim.x) {
        unsigned v = hh[i];
        if (v) atomicAdd(&gh[i], v);
    }
    // ---- fused resolveA: last block of this batch resolves L0 prefixes ----
    __threadfence();
    __syncthreads();
    if (tid == 0) s_last = (atomicAdd(&g_arrive[b], 1) == (int)gridDim.x - 1) ? 1 : 0;
    __syncthreads();
    if (s_last) {
        __threadfence();
        int n = g_cntm[b];
        for (int i = tid; i < NB0; i += blockDim.x) hh[i] = g_hist0[b][i];
        __syncthreads();
        block_exscan_chunks(hh, sPP, NB0 / 256);
        if (tid < 4) {
            unsigned rk[4]; ranks_for_n(n, rk);
            unsigned bin = 0, rem = 0;
            if (n > 0) resolve_one(hh, sPP, NB0 / 256, NB0, rk[tid], &bin, &rem);
            g_pref[b * 4 + tid] = bin;
            g_rem[b * 4 + tid] = rem;
        }
        for (int i = tid; i < NB0; i += blockDim.x) g_hist0[b][i] = 0u;  // replay-safe
        if (tid == 0) g_arrive[b] = 0;   // reused by gather
    }
}

// Gather + full select: smem-staged candidate gather + 8-bit sub-hist counts;
// last block per batch resolves the final quantile values -> g_qv.
__global__ void k_gather() {
    __shared__ unsigned buf[4][LCAP];
    __shared__ unsigned h1s[4][256];
    __shared__ int lcnt[4];
    __shared__ int gbase[4];
    __shared__ unsigned spref[4];
    __shared__ int s_last;
    int b = blockIdx.y, tid = threadIdx.x;
    if (tid < 4) { lcnt[tid] = 0; spref[tid] = g_pref[b * 4 + tid]; }
    for (int i = tid; i < 4 * 256; i += 256) ((unsigned*)h1s)[i] = 0u;
    __syncthreads();
    int n = g_cntm[b];
    unsigned p0 = spref[0], p1 = spref[1], p2 = spref[2], p3 = spref[3];
    const unsigned int* keys = g_keys + (size_t)b * N2;
    const uint4* k4 = (const uint4*)keys;
    int n4 = n >> 2;
    int stride = gridDim.x * blockDim.x;
#define TRY(key, q) { atomicAdd(&h1s[q][((key) >> 12) & 255u], 1u); \
        int p = atomicAdd(&lcnt[q], 1); \
        if (p < LCAP) buf[q][p] = (key); \
        else { int g = atomicAdd(&g_candcnt[b * 4 + q], 1); \
               if (g < CAP) g_cand[(b * 4 + q) * CAP + g] = (key); } }
#define PROC(key) { unsigned hi = (key) >> 20; \
        if (hi == p0) TRY(key, 0) \
        if (hi == p1) TRY(key, 1) \
        if (hi == p2) TRY(key, 2) \
        if (hi == p3) TRY(key, 3) }
    for (int i = blockIdx.x * blockDim.x + tid; i < n4; i += stride) {
        uint4 kk = __ldcs(k4 + i);
        PROC(kk.x) PROC(kk.y) PROC(kk.z) PROC(kk.w)
    }
    if (blockIdx.x == 0) {
        for (int i = (n4 << 2) + tid; i < n; i += blockDim.x) {
            unsigned key = keys[i];
            PROC(key)
        }
    }
#undef PROC
#undef TRY
    __syncthreads();
    if (tid < 4) {
        int c = lcnt[tid]; if (c > LCAP) c = LCAP;
        gbase[tid] = atomicAdd(&g_candcnt[b * 4 + tid], c);
    }
    __syncthreads();
    for (int q = 0; q < 4; q++) {
        int c = lcnt[q]; if (c > LCAP) c = LCAP;
        int base = gbase[q];
        unsigned int* dst = g_cand + (size_t)(b * 4 + q) * CAP;
        for (int i = tid; i < c; i += blockDim.x) {
            int pos = base + i;
            if (pos < CAP) dst[pos] = buf[q][i];
        }
        // flush sub-hist counts
        unsigned v = h1s[q][tid];
        if (v) atomicAdd(&g_hist1[b * 4 + q][tid], v);
    }
    // ---- fused select: last block of this batch computes g_qv ----
    __threadfence();
    __syncthreads();
    if (tid == 0) s_last = (atomicAdd(&g_arrive[b], 1) == (int)gridDim.x - 1) ? 1 : 0;
    __syncthreads();
    if (!s_last) return;
    __threadfence();
    __shared__ unsigned sh[256];
    __shared__ unsigned sP[257];
    __shared__ unsigned slist[SUBCAP];
    __shared__ int slcnt;
    __shared__ unsigned ssub, srem;
    for (int q = 0; q < 4; q++) {
        int bq = b * 4 + q;
        if (n == 0) { if (tid == 0) g_qv[bq] = 0.f; continue; }
        int cnt = g_candcnt[bq];
        if (cnt > CAP) cnt = CAP;
        // resolve 8-bit sub-bin from counts
        sh[tid] = g_hist1[bq][tid];
        __syncthreads();
        block_exscan_chunks(sh, sP, 1);
        if (tid == 0) {
            unsigned bin, rem;
            resolve_one(sh, sP, 1, 256, g_rem[bq], &bin, &rem);
            ssub = bin; srem = rem;
            slcnt = 0;
        }
        __syncthreads();
        unsigned sub = ssub;
        const unsigned int* cd = g_cand + (size_t)bq * CAP;
        for (int i = tid; i < cnt; i += 256) {
            unsigned key = cd[i];
            if (((key >> 12) & 255u) == sub) {
                int p = atomicAdd(&slcnt, 1);
                if (p < SUBCAP) slist[p] = key;
            }
        }
        __syncthreads();
        int m = slcnt; if (m > SUBCAP) m = SUBCAP;
        unsigned r2 = srem;
        // exact rank-r2 selection among m keys (tie-aware)
        for (int i = tid; i < m; i += 256) {
            unsigned x = slist[i];
            unsigned cl = 0, ce = 0;
            for (int j = 0; j < m; j++) {
                unsigned y = slist[j];
                cl += (y < x); ce += (y == x);
            }
            if (cl <= r2 && r2 < cl + ce) g_qv[bq] = kinv(x);   // all writers agree
        }
        // re-zero hist1 slice for replay
        g_hist1[bq][tid] = 0u;
        __syncthreads();
    }
    if (tid == 0) g_arrive[b] = 0;
}

// curr_grad output + static residual compaction + trim L0 hist build.
// Block-aggregated g_cnt reservation. Thread-0 prelude computes scalars.
__global__ void k_compact(const float* __restrict__ prev, float* __restrict__ out) {
    __shared__ float sh_s, sh_th, sh_sc;
    __shared__ unsigned swt[8], swoff[8], sbase;
    int b = blockIdx.y, tid = threadIdx.x;
    if (tid == 0) {
        double a00 = g_sums[b][0], a01 = g_sums[b][1], a11 = g_sums[b][2];
        double bb0 = g_sums[b][3], bb1 = g_sums[b][4];
        double det = a00 * a11 - a01 * a01;
        float s = 0.f;
        if (det != 0.0) {
            double id = 1.0 / (det + 1e-6);
            s = (float)((a11 * bb0 - a01 * bb1) * id);
        }
        int n = g_cntm[b];
        float rr = 1.0f;
        if (n > 0) {
            float v0 = g_qv[b * 4 + 0], v1 = g_qv[b * 4 + 1];
            float v2 = g_qv[b * 4 + 2], v3 = g_qv[b * 4 + 3];
            int nm1 = (n > 1) ? (n - 1) : 0;
            float pos05 = 0.05f * (float)nm1, pos95 = 0.95f * (float)nm1;
            float lo = v0 + (v1 - v0) * (pos05 - floorf(pos05));
            float hi = v2 + (v3 - v2) * (pos95 - floorf(pos95));
            bool valid = isfinite(lo) && isfinite(hi) && (hi - lo > 0.f) &&
                         (fabsf(lo) < 1e30f) && (fabsf(hi) < 1e30f);
            rr = valid ? fmaxf(hi - lo, 1e-6f) : 1.0f;
        }
        sh_s = s; sh_sc = fmaxf(rr, 1e-6f); sh_th = 0.01f * rr;
        if (blockIdx.x == 0) g_rr[b] = rr;
    }
    __syncthreads();
    float s = sh_s, th = sh_th, sc = sh_sc;
    const float4* dp4 = (const float4*)(g_dp  + (size_t)b * NPIX);
    const float4* dg4 = (const float4*)(g_dgt + (size_t)b * NPIX);
    const float4* pv4 = (const float4*)(prev + (size_t)b * NPIX);
    const unsigned char* mm = g_m12 + (size_t)b * NPIX4;
    float4* o4 = (float4*)(out + 4 + (size_t)b * NPIX);
    int lane = tid & 31;
    int wp = tid >> 5;
    int tot_threads = gridDim.x * blockDim.x;
    for (int i = blockIdx.x * blockDim.x + tid; i < NPIX4; i += tot_threads) {
        float4 DP = __ldcs(dp4 + i), DG = __ldcs(dg4 + i), PV = __ldcs(pv4 + i);
        unsigned mbyte = __ldcs(mm + i);
        float4 O;
        unsigned actbits = 0;
        float rdv[4], rav[4];
#define DO(c, idx) { float dp = s * DP.c; O.c = dp; \
        bool st = ((mbyte >> idx) & 1u) && (fabsf(DG.c) < th); \
        if (st) actbits |= (1u << idx); \
        rdv[idx] = fabsf(dp - DG.c) / sc; rav[idx] = fabsf(dp - PV.c) / sc; }
        DO(x, 0) DO(y, 1) DO(z, 2) DO(w, 3)
#undef DO
        __stcs(o4 + i, O);
        int tot = __popc(actbits), excl, wtot;
        warp_exscan(tot, lane, &excl, &wtot);
        if (lane == 0) swt[wp] = (unsigned)wtot;
        __syncthreads();
        if (tid == 0) {
            unsigned acc = 0;
            for (int w = 0; w < 8; w++) { swoff[w] = acc; acc += swt[w]; }
            sbase = acc ? (unsigned)atomicAdd(&g_cnt[b], (int)acc) : 0u;
        }
        __syncthreads();
        if (actbits) {
            unsigned pos = sbase + swoff[wp] + (unsigned)excl;
#pragma unroll
            for (int q = 0; q < 4; q++) {
                if (actbits & (1u << q)) {
                    unsigned kd = fkey(rdv[q]), ka = fkey(rav[q]);
                    g_rd_keys[(size_t)b * NPIX + pos] = kd;
                    g_ra_keys[(size_t)b * NPIX + pos] = ka;
                    atomicAdd(&g_histt[b * 2 + 0][kd >> 21], 1u);
                    atomicAdd(&g_histt[b * 2 + 1][ka >> 21], 1u);
                    pos++;
                }
            }
        }
    }
}

// Trimmed-huber: per (batch, j) block. L0 resolved from precomputed g_histt;
// levels 1-2 + huber sum over smem-cached keys. Last block does the final
// reduction + all replay re-zeroing.
__global__ void k_trim(float* __restrict__ out) {
    __shared__ unsigned int skeys[8192];
    __shared__ unsigned int sh[2048];
    __shared__ unsigned int sP[257];
    __shared__ unsigned int s_prefix, s_rank;
    __shared__ int s_last;
    int tid = threadIdx.x;
    int b = blockIdx.y, j = blockIdx.x;
    int bj = b * 2 + j;
    const unsigned int* gkeys = (j ? g_ra_keys : g_rd_keys) + (size_t)b * NPIX;
    int cnt = g_cnt[b];
    int k = (int)floorf(0.6f * (float)cnt);
    if (k > 0) {
        bool insm = (cnt <= 8192);
        if (insm) for (int i = tid; i < cnt; i += 256) skeys[i] = gkeys[i];
        const unsigned int* keys = insm ? skeys : gkeys;
        for (int i = tid; i < 2048; i += 256) sh[i] = g_histt[bj][i];
        __syncthreads();
        block_exscan_chunks(sh, sP, 8);
        if (tid == 0) {
            unsigned bin, rem;
            resolve_one(sh, sP, 8, 2048, (unsigned)(k - 1), &bin, &rem);
            s_prefix = bin; s_rank = rem;
        }
        __syncthreads();
        for (int level = 1; level < 3; level++) {
            int nb = (level == 2) ? 1024 : 2048;
            for (int i = tid; i < nb; i += 256) sh[i] = 0u;
            __syncthreads();
            unsigned pref = s_prefix;
            for (int i = tid; i < cnt; i += 256) {
                unsigned key = keys[i];
                if (level == 1) { if ((key >> 21) == pref) atomicAdd(&sh[(key >> 10) & 2047u], 1u); }
                else            { if ((key >> 10) == pref) atomicAdd(&sh[key & 1023u], 1u); }
            }
            __syncthreads();
            block_exscan_chunks(sh, sP, nb / 256);
            if (tid == 0) {
                unsigned bin, rem;
                resolve_one(sh, sP, nb / 256, nb, s_rank, &bin, &rem);
                s_rank = rem;
                s_prefix = pref * (unsigned)nb + bin;
            }
            __syncthreads();
        }
        unsigned target = s_prefix;
        float sum = 0.f;
        unsigned less = 0;
        for (int i = tid; i < cnt; i += 256) {
            unsigned key = keys[i];
            if (key < target) { sum += hubf(kinv(key)); less++; }
        }
        for (int o = 16; o > 0; o >>= 1) {
            sum  += __shfl_down_sync(0xffffffffu, sum, o);
            less += __shfl_down_sync(0xffffffffu, less, o);
        }
        __shared__ float ss[8];
        __shared__ unsigned sl[8];
        int lane = tid & 31, wp = tid >> 5;
        if (lane == 0) { ss[wp] = sum; sl[wp] = less; }
        __syncthreads();
        if (tid == 0) {
            float S = 0.f; unsigned L = 0;
            for (int w = 0; w < 8; w++) { S += ss[w]; L += sl[w]; }
            float ht = hubf(kinv(target));
            g_loss[bj] = (S + (float)(k - (int)L) * ht) / (float)k;
        }
    } else {
        if (tid == 0) g_loss[bj] = 0.f;
    }
    for (int i = tid; i < 2048; i += 256) g_histt[bj][i] = 0u;   // replay-safe
    __threadfence();
    __syncthreads();
    if (tid == 0) s_last = (atomicAdd(&g_done, 1) == 31) ? 1 : 0;
    __syncthreads();
    if (s_last) {
        __threadfence();
        if (tid < BB) {
            for (int jj = 0; jj < 5; jj++) g_sums[tid][jj] = 0.0;
            g_cntm[tid] = 0;
            g_cnt[tid] = 0;
            for (int q = 0; q < 4; q++) g_candcnt[tid * 4 + q] = 0;
        }
        if (tid == 0) {
            float sld = 0.f, sla = 0.f, srr = 0.f;
            for (int i = 0; i < BB; i++) {
                sld += g_loss[i * 2];
                sla += g_loss[i * 2 + 1];
                srr += g_rr[i];
            }
            float loss_data = sld / (float)BB;
            float loss_acc  = sla / (float)BB;
            out[0] = loss_data + 0.2f * loss_acc;
            out[1] = loss_data;
            out[2] = loss_acc;
            out[3] = srr / (float)BB;
            g_done = 0;   // replay-safe
        }
    }
}

extern "C" void kernel_launch(void* const* d_in, const int* in_sizes, int n_in,
                              void* d_out, int out_size) {
    const float* pred = (const float*)d_in[0];
    const float* gt   = (const float*)d_in[1];
    const float* mask = (const float*)d_in[2];
    const float* prev = (const float*)d_in[3];
    float* out = (float*)d_out;
    dim3 big(60, BB);

    k_stats<<<big, 256>>>(pred, gt, mask);     // + fused resolveA tail
    k_gather<<<big, 256>>>();                  // + fused quantile select tail
    k_compact<<<big, 256>>>(prev, out);
    k_trim<<<dim3(2, BB), 256>>>(out);         // + fused final reduction
}

// round 14
// speedup vs baseline: 1.1481x; 1.1481x over previous
#include <cuda_runtime.h>
#include <math.h>

#define BB 16
#define NPIX 245760          // 384*640
#define NPIX4 (NPIX/4)
#define N2  491520           // 2*NPIX
#define CAP 16384            // global candidate buffer per (batch,query)
#define LCAP 768             // per-block smem staging per query (gather)
#define NB0 4096             // L0 bins (12-bit prefix)
#define KREG 32              // per-thread register key cache (resolveB)
#define SELTH 512            // direct counting-select threshold (trim)

// ---------------- scratch (static device memory; no runtime allocs) ----------------
__device__ double g_sums[BB][5];                      // a00,a01,a11,b0,b1
__device__ int    g_cntm[BB];                         // masked gt count (= n)
__device__ int    g_cnt[BB];                          // static-pixel count
__device__ int    g_arrive[BB];                       // stats last-block counters
__device__ float  g_rr[BB];
__device__ float  g_loss[32];
__device__ float  g_qv[64];                           // per (b,q) quantile value
__device__ unsigned int g_pref[64], g_rem[64];        // per (b,q): 12-bit L0 prefix, residual rank
__device__ int    g_candcnt[64];
__device__ int    g_done;                             // trim last-block counter
__device__ unsigned int g_hist0[BB][NB0];
__device__ unsigned int g_histt[32][2048];            // built in compact
__device__ unsigned int g_cand[64 * CAP];             // 4 MB
__device__ unsigned int g_keys[(size_t)BB * N2];      // compacted masked gt keys
__device__ unsigned int g_rd_keys[(size_t)BB * NPIX];
__device__ unsigned int g_ra_keys[(size_t)BB * NPIX];
__device__ float  g_dp [(size_t)BB * NPIX];
__device__ float  g_dgt[(size_t)BB * NPIX];
__device__ unsigned char g_m12[(size_t)BB * NPIX4];

// ---------------- helpers ----------------
__device__ __forceinline__ unsigned int fkey(float x) {
    unsigned int u = __float_as_uint(x);
    return (u & 0x80000000u) ? ~u : (u | 0x80000000u);
}
__device__ __forceinline__ float kinv(unsigned int k) {
    unsigned int u = (k & 0x80000000u) ? (k & 0x7fffffffu) : ~k;
    return __uint_as_float(u);
}
__device__ __forceinline__ float hubf(float v) {
    return (v <= 0.03f) ? (0.5f * (v * v)) / 0.03f : (v - 0.015f);
}

// Warp exclusive scan of per-thread count; returns (excl, warp_total).
__device__ __forceinline__ void warp_exscan(int tot, int lane, int* excl, int* wtot) {
    int v = tot;
#pragma unroll
    for (int o = 1; o < 32; o <<= 1) {
        int t = __shfl_up_sync(0xffffffffu, v, o);
        if (lane >= o) v += t;
    }
    *excl = v - tot;
    *wtot = __shfl_sync(0xffffffffu, v, 31);
}

// 256-thread block: exclusive scan of per-thread value s -> sP[0..256]. Ends synced.
__device__ __forceinline__ void scan256(unsigned s, unsigned* sP) {
    int tid = threadIdx.x, lane = tid & 31, wp = tid >> 5;
    unsigned v = s;
#pragma unroll
    for (int o = 1; o < 32; o <<= 1) {
        unsigned t = __shfl_up_sync(0xffffffffu, v, o);
        if (lane >= o) v += t;
    }
    __shared__ unsigned wtot[8];
    if (lane == 31) wtot[wp] = v;
    __syncthreads();
    unsigned wo = 0;
    for (int w = 0; w < wp; w++) wo += wtot[w];
    unsigned excl = wo + v - s;
    sP[tid] = excl;
    if (tid == 255) sP[256] = excl + s;
    __syncthreads();
}

__device__ __forceinline__ void block_exscan_chunks(const unsigned int* sh,
                                                    unsigned int* sP, int chunk) {
    int tid = threadIdx.x;
    unsigned s = 0;
#pragma unroll 4
    for (int j = 0; j < chunk; j++) s += sh[tid * chunk + j];
    scan256(s, sP);
}

__device__ __forceinline__ int bsearch256(const unsigned int* sP, unsigned rank) {
    int lo = 0, hi = 255;
    while (lo < hi) {
        int mid = (lo + hi + 1) >> 1;
        if (sP[mid] <= rank) lo = mid; else hi = mid - 1;
    }
    return lo;
}

__device__ __forceinline__ void resolve_one(const unsigned int* sh, const unsigned int* sP,
                                            int chunk, int nb, unsigned rank,
                                            unsigned* bin_out, unsigned* rem_out) {
    int lo = bsearch256(sP, rank);
    unsigned cum = sP[lo];
    int bin = lo * chunk;
    int end = bin + chunk;
    if (end > nb) end = nb;
    while (bin + 1 < end && cum + sh[bin] <= rank) { cum += sh[bin]; bin++; }
    *bin_out = (unsigned)bin;
    *rem_out = rank - cum;
}

__device__ __forceinline__ void ranks_for_n(int n, unsigned* r) {
    int nm1 = (n > 1) ? (n - 1) : 0;
    float pos05 = 0.05f * (float)nm1;
    float pos95 = 0.95f * (float)nm1;
    r[0] = (unsigned)floorf(pos05);
    r[1] = (unsigned)ceilf(pos05);
    r[2] = (unsigned)floorf(pos95);
    r[3] = (unsigned)ceilf(pos95);
}

// ---------------- kernels ----------------
// Pass 1: moments + compacted gt keys + smem hist L0 (12-bit) + dp/dgt/m12 precompute.
// Block-aggregated counter reservation. Last block per batch resolves L0 prefixes.
__global__ void k_stats(const float* __restrict__ pred, const float* __restrict__ gt,
                        const float* __restrict__ mask) {
    __shared__ unsigned int hh[NB0];
    __shared__ unsigned int sPP[257];
    __shared__ unsigned swt[8];      // per-warp totals
    __shared__ unsigned swoff[8];    // per-warp offsets
    __shared__ unsigned sbase;
    __shared__ int s_last;
    int b = blockIdx.y;
    int tid = threadIdx.x;
    for (int i = tid; i < NB0; i += blockDim.x) hh[i] = 0u;
    __syncthreads();
    const float4* p0 = (const float4*)(pred + (size_t)b * N2);
    const float4* p1 = (const float4*)(pred + (size_t)b * N2 + NPIX);
    const float4* g0 = (const float4*)(gt   + (size_t)b * N2);
    const float4* g1 = (const float4*)(gt   + (size_t)b * N2 + NPIX);
    const float4* m0 = (const float4*)(mask + (size_t)b * N2);
    const float4* m1 = (const float4*)(mask + (size_t)b * N2 + NPIX);
    float4* dp4  = (float4*)(g_dp  + (size_t)b * NPIX);
    float4* dg4  = (float4*)(g_dgt + (size_t)b * NPIX);
    unsigned char* mm = g_m12 + (size_t)b * NPIX4;
    unsigned int* keys = g_keys + (size_t)b * N2;
    float a00 = 0.f, a01 = 0.f, a11 = 0.f, bb0 = 0.f, bb1 = 0.f;
    int lane = tid & 31;
    int wp = tid >> 5;
    int tot_threads = gridDim.x * blockDim.x;
    for (int i = blockIdx.x * blockDim.x + tid; i < NPIX4; i += tot_threads) {
        float4 P0 = __ldcs(p0 + i), P1 = __ldcs(p1 + i);
        float4 G0 = __ldcs(g0 + i), G1 = __ldcs(g1 + i);
        float4 M0 = __ldcs(m0 + i), M1 = __ldcs(m1 + i);
        float4 dpv, dgv;
        unsigned kv[8];
        unsigned actbits = 0, mbyte = 0;
#define DO(c, idx, bit) { bool a0 = M0.c > 0.5f, a1 = M1.c > 0.5f; \
        if (a0) { a00 += P0.c * P0.c; a01 += P0.c; a11 += 1.f; bb0 += P0.c * G0.c; bb1 += G0.c; } \
        if (a1) { a00 += P1.c * P1.c; a01 += P1.c; a11 += 1.f; bb0 += P1.c * G1.c; bb1 += G1.c; } \
        if (a0) actbits |= (1u << idx); kv[idx] = fkey(G0.c); \
        if (a1) actbits |= (1u << (idx + 4)); kv[idx + 4] = fkey(G1.c); \
        if (a0 && a1) mbyte |= (1u << bit); \
        dpv.c = P1.c - P0.c; dgv.c = G1.c - G0.c; }
        DO(x, 0, 0) DO(y, 1, 1) DO(z, 2, 2) DO(w, 3, 3)
#undef DO
        int tot = __popc(actbits), excl, wtot;
        warp_exscan(tot, lane, &excl, &wtot);
        if (lane == 0) swt[wp] = (unsigned)wtot;
        __syncthreads();
        if (tid == 0) {
            unsigned acc = 0;
            for (int w = 0; w < 8; w++) { swoff[w] = acc; acc += swt[w]; }
            sbase = acc ? (unsigned)atomicAdd(&g_cntm[b], (int)acc) : 0u;
        }
        __syncthreads();
        unsigned pos = sbase + swoff[wp] + (unsigned)excl;
#pragma unroll
        for (int s = 0; s < 8; s++) {
            if (actbits & (1u << s)) {
                keys[pos] = kv[s];
                atomicAdd(&hh[kv[s] >> 20], 1u);
                pos++;
            }
        }
        dp4[i] = dpv; dg4[i] = dgv; mm[i] = (unsigned char)mbyte;
    }
    double d0 = a00, d1 = a01, d2 = a11, d3 = bb0, d4 = bb1;
    for (int off = 16; off > 0; off >>= 1) {
        d0 += __shfl_down_sync(0xffffffffu, d0, off);
        d1 += __shfl_down_sync(0xffffffffu, d1, off);
        d2 += __shfl_down_sync(0xffffffffu, d2, off);
        d3 += __shfl_down_sync(0xffffffffu, d3, off);
        d4 += __shfl_down_sync(0xffffffffu, d4, off);
    }
    __shared__ double shd[8][5];
    if (lane == 0) { shd[wp][0] = d0; shd[wp][1] = d1; shd[wp][2] = d2; shd[wp][3] = d3; shd[wp][4] = d4; }
    __syncthreads();
    if (tid == 0) {
        double s0 = 0, s1 = 0, s2 = 0, s3 = 0, s4 = 0;
        for (int w = 0; w < 8; w++) { s0 += shd[w][0]; s1 += shd[w][1]; s2 += shd[w][2]; s3 += shd[w][3]; s4 += shd[w][4]; }
        atomicAdd(&g_sums[b][0], s0); atomicAdd(&g_sums[b][1], s1);
        atomicAdd(&g_sums[b][2], s2); atomicAdd(&g_sums[b][3], s3);
        atomicAdd(&g_sums[b][4], s4);
    }
    unsigned int* gh = g_hist0[b];
    for (int i = tid; i < NB0; i += blockDim.x) {
        unsigned v = hh[i];
        if (v) atomicAdd(&gh[i], v);
    }
    // ---- fused resolveA: last block of this batch resolves L0 prefixes ----
    __threadfence();
    __syncthreads();
    if (tid == 0) s_last = (atomicAdd(&g_arrive[b], 1) == (int)gridDim.x - 1) ? 1 : 0;
    __syncthreads();
    if (s_last) {
        __threadfence();
        int n = g_cntm[b];
        for (int i = tid; i < NB0; i += blockDim.x) hh[i] = g_hist0[b][i];
        __syncthreads();
        block_exscan_chunks(hh, sPP, NB0 / 256);
        if (tid < 4) {
            unsigned rk[4]; ranks_for_n(n, rk);
            unsigned bin = 0, rem = 0;
            if (n > 0) resolve_one(hh, sPP, NB0 / 256, NB0, rk[tid], &bin, &rem);
            g_pref[b * 4 + tid] = bin;
            g_rem[b * 4 + tid] = rem;
        }
        for (int i = tid; i < NB0; i += blockDim.x) g_hist0[b][i] = 0u;  // replay-safe
        if (tid == 0) g_arrive[b] = 0;
    }
}

// One pass over compacted keys: smem-staged candidate gather.
__global__ void k_gather() {
    __shared__ unsigned buf[4][LCAP];
    __shared__ int lcnt[4];
    __shared__ int gbase[4];
    __shared__ unsigned spref[4];
    int b = blockIdx.y, tid = threadIdx.x;
    if (tid < 4) { lcnt[tid] = 0; spref[tid] = g_pref[b * 4 + tid]; }
    __syncthreads();
    int n = g_cntm[b];
    unsigned p0 = spref[0], p1 = spref[1], p2 = spref[2], p3 = spref[3];
    const unsigned int* keys = g_keys + (size_t)b * N2;
    const uint4* k4 = (const uint4*)keys;
    int n4 = n >> 2;
    int stride = gridDim.x * blockDim.x;
#define TRY(key, q) { int p = atomicAdd(&lcnt[q], 1); \
        if (p < LCAP) buf[q][p] = (key); \
        else { int g = atomicAdd(&g_candcnt[b * 4 + q], 1); \
               if (g < CAP) g_cand[(b * 4 + q) * CAP + g] = (key); } }
#define PROC(key) { unsigned hi = (key) >> 20; \
        if (hi == p0) TRY(key, 0) \
        if (hi == p1) TRY(key, 1) \
        if (hi == p2) TRY(key, 2) \
        if (hi == p3) TRY(key, 3) }
    for (int i = blockIdx.x * blockDim.x + tid; i < n4; i += stride) {
        uint4 kk = __ldcs(k4 + i);
        PROC(kk.x) PROC(kk.y) PROC(kk.z) PROC(kk.w)
    }
    if (blockIdx.x == 0) {
        for (int i = (n4 << 2) + tid; i < n; i += blockDim.x) {
            unsigned key = keys[i];
            PROC(key)
        }
    }
#undef PROC
#undef TRY
    __syncthreads();
    if (tid < 4) {
        int c = lcnt[tid]; if (c > LCAP) c = LCAP;
        gbase[tid] = atomicAdd(&g_candcnt[b * 4 + tid], c);
    }
    __syncthreads();
    for (int q = 0; q < 4; q++) {
        int c = lcnt[q]; if (c > LCAP) c = LCAP;
        int base = gbase[q];
        unsigned int* dst = g_cand + (size_t)(b * 4 + q) * CAP;
        for (int i = tid; i < c; i += blockDim.x) {
            int pos = base + i;
            if (pos < CAP) dst[pos] = buf[q][i];
        }
    }
}

// grid=(4,BB): one block per (batch,query). Candidates read once into registers;
// 11-bit mid [9:20) + 9-bit low [0:9) select entirely from smem hists -> g_qv.
__global__ void k_resolveB() {
    __shared__ unsigned sh[2048];
    __shared__ unsigned sP[257];
    __shared__ unsigned sbin, srem;
    int q = blockIdx.x, b = blockIdx.y, tid = threadIdx.x;
    int bq = b * 4 + q;
    int n = g_cntm[b];
    if (n == 0) { if (tid == 0) g_qv[bq] = 0.f; return; }
    int cnt = g_candcnt[bq];
    if (cnt > CAP) cnt = CAP;
    unsigned rank = g_rem[bq];
    const unsigned int* gcd = g_cand + (size_t)bq * CAP;
    unsigned kbuf[KREG];
    int nk = 0;
    for (int i = tid; i < cnt && nk < KREG; i += 256) kbuf[nk++] = gcd[i];
    for (int i = tid; i < 2048; i += 256) sh[i] = 0u;
    __syncthreads();
    {
        int kk = 0;
        for (int i = tid; i < cnt; i += 256, kk++) {
            unsigned key = (kk < KREG) ? kbuf[kk] : gcd[i];
            atomicAdd(&sh[(key >> 9) & 2047u], 1u);
        }
    }
    __syncthreads();
    block_exscan_chunks(sh, sP, 8);
    if (tid == 0) {
        unsigned bin, rem;
        resolve_one(sh, sP, 8, 2048, rank, &bin, &rem);
        sbin = bin; srem = rem;
    }
    __syncthreads();
    unsigned binM = sbin, remM = srem;
    for (int i = tid; i < 512; i += 256) sh[i] = 0u;
    __syncthreads();
    {
        int kk = 0;
        for (int i = tid; i < cnt; i += 256, kk++) {
            unsigned key = (kk < KREG) ? kbuf[kk] : gcd[i];
            if (((key >> 9) & 2047u) == binM) atomicAdd(&sh[key & 511u], 1u);
        }
    }
    __syncthreads();
    block_exscan_chunks(sh, sP, 2);
    if (tid == 0) {
        unsigned bin, rem;
        resolve_one(sh, sP, 2, 512, remM, &bin, &rem);
        unsigned full = (g_pref[bq] << 20) | (binM << 9) | bin;
        g_qv[bq] = kinv(full);
    }
}

// curr_grad output + static residual compaction + trim L0 hist build.
// Block-aggregated g_cnt reservation. Thread-0 prelude computes scalars.
__global__ void k_compact(const float* __restrict__ prev, float* __restrict__ out) {
    __shared__ float sh_s, sh_th, sh_sc;
    __shared__ unsigned swt[8], swoff[8], sbase;
    int b = blockIdx.y, tid = threadIdx.x;
    if (tid == 0) {
        double a00 = g_sums[b][0], a01 = g_sums[b][1], a11 = g_sums[b][2];
        double bb0 = g_sums[b][3], bb1 = g_sums[b][4];
        double det = a00 * a11 - a01 * a01;
        float s = 0.f;
        if (det != 0.0) {
            double id = 1.0 / (det + 1e-6);
            s = (float)((a11 * bb0 - a01 * bb1) * id);
        }
        int n = g_cntm[b];
        float rr = 1.0f;
        if (n > 0) {
            float v0 = g_qv[b * 4 + 0], v1 = g_qv[b * 4 + 1];
            float v2 = g_qv[b * 4 + 2], v3 = g_qv[b * 4 + 3];
            int nm1 = (n > 1) ? (n - 1) : 0;
            float pos05 = 0.05f * (float)nm1, pos95 = 0.95f * (float)nm1;
            float lo = v0 + (v1 - v0) * (pos05 - floorf(pos05));
            float hi = v2 + (v3 - v2) * (pos95 - floorf(pos95));
            bool valid = isfinite(lo) && isfinite(hi) && (hi - lo > 0.f) &&
                         (fabsf(lo) < 1e30f) && (fabsf(hi) < 1e30f);
            rr = valid ? fmaxf(hi - lo, 1e-6f) : 1.0f;
        }
        sh_s = s; sh_sc = fmaxf(rr, 1e-6f); sh_th = 0.01f * rr;
        if (blockIdx.x == 0) g_rr[b] = rr;
    }
    __syncthreads();
    float s = sh_s, th = sh_th, sc = sh_sc;
    const float4* dp4 = (const float4*)(g_dp  + (size_t)b * NPIX);
    const float4* dg4 = (const float4*)(g_dgt + (size_t)b * NPIX);
    const float4* pv4 = (const float4*)(prev + (size_t)b * NPIX);
    const unsigned char* mm = g_m12 + (size_t)b * NPIX4;
    float4* o4 = (float4*)(out + 4 + (size_t)b * NPIX);
    int lane = tid & 31;
    int wp = tid >> 5;
    int tot_threads = gridDim.x * blockDim.x;
    for (int i = blockIdx.x * blockDim.x + tid; i < NPIX4; i += tot_threads) {
        float4 DP = __ldcs(dp4 + i), DG = __ldcs(dg4 + i), PV = __ldcs(pv4 + i);
        unsigned mbyte = __ldcs(mm + i);
        float4 O;
        unsigned actbits = 0;
        float rdv[4], rav[4];
#define DO(c, idx) { float dp = s * DP.c; O.c = dp; \
        bool st = ((mbyte >> idx) & 1u) && (fabsf(DG.c) < th); \
        if (st) actbits |= (1u << idx); \
        rdv[idx] = fabsf(dp - DG.c) / sc; rav[idx] = fabsf(dp - PV.c) / sc; }
        DO(x, 0) DO(y, 1) DO(z, 2) DO(w, 3)
#undef DO
        __stcs(o4 + i, O);
        int tot = __popc(actbits), excl, wtot;
        warp_exscan(tot, lane, &excl, &wtot);
        if (lane == 0) swt[wp] = (unsigned)wtot;
        __syncthreads();
        if (tid == 0) {
            unsigned acc = 0;
            for (int w = 0; w < 8; w++) { swoff[w] = acc; acc += swt[w]; }
            sbase = acc ? (unsigned)atomicAdd(&g_cnt[b], (int)acc) : 0u;
        }
        __syncthreads();
        if (actbits) {
            unsigned pos = sbase + swoff[wp] + (unsigned)excl;
#pragma unroll
            for (int q = 0; q < 4; q++) {
                if (actbits & (1u << q)) {
                    unsigned kd = fkey(rdv[q]), ka = fkey(rav[q]);
                    g_rd_keys[(size_t)b * NPIX + pos] = kd;
                    g_ra_keys[(size_t)b * NPIX + pos] = ka;
                    atomicAdd(&g_histt[b * 2 + 0][kd >> 21], 1u);
                    atomicAdd(&g_histt[b * 2 + 1][ka >> 21], 1u);
                    pos++;
                }
            }
        }
    }
}

// Trimmed-huber: per (batch, j) block. L0 from precomputed g_histt, then
// collect winning-bin keys and do an exact tie-aware counting select
// (one radix fallback level if the bin is large). Last block reduces + re-zeroes.
__global__ void k_trim(float* __restrict__ out) {
    __shared__ unsigned int skeys[8192];
    __shared__ unsigned int slist[8192];
    __shared__ unsigned int sh[2048];
    __shared__ unsigned int sP[257];
    __shared__ unsigned int s_target;
    __shared__ int slcnt, sl2cnt;
    __shared__ unsigned sbin, srem;
    __shared__ int s_last;
    int tid = threadIdx.x;
    int b = blockIdx.y, j = blockIdx.x;
    int bj = b * 2 + j;
    const unsigned int* gkeys = (j ? g_ra_keys : g_rd_keys) + (size_t)b * NPIX;
    int cnt = g_cnt[b];
    int k = (int)floorf(0.6f * (float)cnt);
    if (k > 0) {
        bool insm = (cnt <= 8192);
        if (insm) for (int i = tid; i < cnt; i += 256) skeys[i] = gkeys[i];
        const unsigned int* keys = insm ? skeys : gkeys;
        // L0 from precomputed hist (bits >=21)
        for (int i = tid; i < 2048; i += 256) sh[i] = g_histt[bj][i];
        __syncthreads();
        block_exscan_chunks(sh, sP, 8);
        if (tid == 0) {
            unsigned bin, rem;
            resolve_one(sh, sP, 8, 2048, (unsigned)(k - 1), &bin, &rem);
            sbin = bin; srem = rem;
            slcnt = 0;
        }
        __syncthreads();
        unsigned bin0 = sbin;
        // collect keys in the winning L0 bin
        for (int i = tid; i < cnt; i += 256) {
            unsigned key = keys[i];
            if ((key >> 21) == bin0) {
                int p = atomicAdd(&slcnt, 1);
                if (p < 8192) slist[p] = key;
            }
        }
        __syncthreads();
        int m = slcnt; if (m > 8192) m = 8192;
        unsigned r = srem;
        if (m <= SELTH) {
            // exact tie-aware counting select over m keys
            for (int i = tid; i < m; i += 256) {
                unsigned x = slist[i];
                unsigned cl = 0, ce = 0;
                for (int jj = 0; jj < m; jj++) {
                    unsigned y = slist[jj];
                    cl += (y < x); ce += (y == x);
                }
                if (cl <= r && r < cl + ce) s_target = x;   // all writers agree
            }
            __syncthreads();
        } else {
            // one radix level on bits [10:21), then counting select
            for (int i = tid; i < 2048; i += 256) sh[i] = 0u;
            __syncthreads();
            for (int i = tid; i < m; i += 256) atomicAdd(&sh[(slist[i] >> 10) & 2047u], 1u);
            __syncthreads();
            block_exscan_chunks(sh, sP, 8);
            if (tid == 0) {
                unsigned bin, rem;
                resolve_one(sh, sP, 8, 2048, r, &bin, &rem);
                sbin = bin; srem = rem;
                sl2cnt = 0;
            }
            __syncthreads();
            unsigned bin1 = sbin;
            // compact matching keys to the tail half of slist (no overlap: m <= 8192/2 ? not guaranteed;
            // use sh as 2048-cap list — matches of a single 2048-bin among m keys)
            for (int i = tid; i < m; i += 256) {
                unsigned key = slist[i];
                if (((key >> 10) & 2047u) == bin1) {
                    int p = atomicAdd(&sl2cnt, 1);
                    if (p < 2048) sh[p] = key;
                }
            }
            __syncthreads();
            int m2 = sl2cnt; if (m2 > 2048) m2 = 2048;
            unsigned r2 = srem;
            for (int i = tid; i < m2; i += 256) {
                unsigned x = sh[i];
                unsigned cl = 0, ce = 0;
                for (int jj = 0; jj < m2; jj++) {
                    unsigned y = sh[jj];
                    cl += (y < x); ce += (y == x);
                }
                if (cl <= r2 && r2 < cl + ce) s_target = x;
            }
            __syncthreads();
        }
        unsigned target = s_target;
        float sum = 0.f;
        unsigned less = 0;
        for (int i = tid; i < cnt; i += 256) {
            unsigned key = keys[i];
            if (key < target) { sum += hubf(kinv(key)); less++; }
        }
        for (int o = 16; o > 0; o >>= 1) {
            sum  += __shfl_down_sync(0xffffffffu, sum, o);
            less += __shfl_down_sync(0xffffffffu, less, o);
        }
        __shared__ float ss[8];
        __shared__ unsigned sl[8];
        int lane = tid & 31, wp = tid >> 5;
        if (lane == 0) { ss[wp] = sum; sl[wp] = less; }
        __syncthreads();
        if (tid == 0) {
            float S = 0.f; unsigned L = 0;
            for (int w = 0; w < 8; w++) { S += ss[w]; L += sl[w]; }
            float ht = hubf(kinv(target));
            g_loss[bj] = (S + (float)(k - (int)L) * ht) / (float)k;
        }
    } else {
        if (tid == 0) g_loss[bj] = 0.f;
    }
    for (int i = tid; i < 2048; i += 256) g_histt[bj][i] = 0u;   // replay-safe
    __threadfence();
    __syncthreads();
    if (tid == 0) s_last = (atomicAdd(&g_done, 1) == 31) ? 1 : 0;
    __syncthreads();
    if (s_last) {
        __threadfence();
        if (tid < BB) {
            for (int jj = 0; jj < 5; jj++) g_sums[tid][jj] = 0.0;
            g_cntm[tid] = 0;
            g_cnt[tid] = 0;
            for (int q = 0; q < 4; q++) g_candcnt[tid * 4 + q] = 0;
        }
        if (tid == 0) {
            float sld = 0.f, sla = 0.f, srr = 0.f;
            for (int i = 0; i < BB; i++) {
                sld += g_loss[i * 2];
                sla += g_loss[i * 2 + 1];
                srr += g_rr[i];
            }
            float loss_data = sld / (float)BB;
            float loss_acc  = sla / (float)BB;
            out[0] = loss_data + 0.2f * loss_acc;
            out[1] = loss_data;
            out[2] = loss_acc;
            out[3] = srr / (float)BB;
            g_done = 0;   // replay-safe
        }
    }
}

extern "C" void kernel_launch(void* const* d_in, const int* in_sizes, int n_in,
                              void* d_out, int out_size) {
    const float* pred = (const float*)d_in[0];
    const float* gt   = (const float*)d_in[1];
    const float* mask = (const float*)d_in[2];
    const float* prev = (const float*)d_in[3];
    float* out = (float*)d_out;
    dim3 big(60, BB);

    k_stats<<<big, 256>>>(pred, gt, mask);     // + fused resolveA tail
    k_gather<<<big, 256>>>();
    k_resolveB<<<dim3(4, BB), 256>>>();
    k_compact<<<big, 256>>>(prev, out);
    k_trim<<<dim3(2, BB), 256>>>(out);         // + fused final reduction
}

// round 15
// speedup vs baseline: 1.1531x; 1.0043x over previous
#include <cuda_runtime.h>
#include <math.h>

#define BB 16
#define NPIX 245760          // 384*640
#define NPIX4 (NPIX/4)
#define N2  491520           // 2*NPIX
#define CAP 16384            // global candidate buffer per (batch,query)
#define LCAP 768             // per-block smem staging per query (gather)
#define NB0 4096             // L0 bins (12-bit prefix)
#define KREG 32              // per-thread register key cache (resolveB)
#define SELTH 512            // direct counting-select threshold (trim)
#define RBSEL 256            // resolveB mid-bin collect cap

// ---------------- scratch (static device memory; no runtime allocs) ----------------
__device__ double g_sums[BB][5];                      // a00,a01,a11,b0,b1
__device__ int    g_cntm[BB];                         // masked gt count (= n)
__device__ int    g_cnt[BB];                          // static-pixel count
__device__ int    g_arrive[BB];                       // stats last-block counters
__device__ float  g_rr[BB];
__device__ float  g_loss[32];
__device__ float  g_qv[64];                           // per (b,q) quantile value
__device__ unsigned int g_pref[64], g_rem[64];        // per (b,q): 12-bit L0 prefix, residual rank
__device__ int    g_candcnt[64];
__device__ int    g_done;                             // trim last-block counter
__device__ unsigned int g_hist0[BB][NB0];
__device__ unsigned int g_histt[32][2048];            // built in compact
__device__ unsigned int g_cand[64 * CAP];             // 4 MB
__device__ unsigned int g_keys[(size_t)BB * N2];      // compacted masked gt keys
__device__ unsigned int g_rd_keys[(size_t)BB * NPIX];
__device__ unsigned int g_ra_keys[(size_t)BB * NPIX];
__device__ float  g_dp [(size_t)BB * NPIX];
__device__ float  g_dgt[(size_t)BB * NPIX];
__device__ unsigned char g_m12[(size_t)BB * NPIX4];

// ---------------- helpers ----------------
__device__ __forceinline__ unsigned int fkey(float x) {
    unsigned int u = __float_as_uint(x);
    return (u & 0x80000000u) ? ~u : (u | 0x80000000u);
}
__device__ __forceinline__ float kinv(unsigned int k) {
    unsigned int u = (k & 0x80000000u) ? (k & 0x7fffffffu) : ~k;
    return __uint_as_float(u);
}
__device__ __forceinline__ float hubf(float v) {
    return (v <= 0.03f) ? (0.5f * (v * v)) / 0.03f : (v - 0.015f);
}

// Warp exclusive scan of per-thread count; returns (excl, warp_total).
__device__ __forceinline__ void warp_exscan(int tot, int lane, int* excl, int* wtot) {
    int v = tot;
#pragma unroll
    for (int o = 1; o < 32; o <<= 1) {
        int t = __shfl_up_sync(0xffffffffu, v, o);
        if (lane >= o) v += t;
    }
    *excl = v - tot;
    *wtot = __shfl_sync(0xffffffffu, v, 31);
}

// 256-thread block: exclusive scan of per-thread value s -> sP[0..256]. Ends synced.
__device__ __forceinline__ void scan256(unsigned s, unsigned* sP) {
    int tid = threadIdx.x, lane = tid & 31, wp = tid >> 5;
    unsigned v = s;
#pragma unroll
    for (int o = 1; o < 32; o <<= 1) {
        unsigned t = __shfl_up_sync(0xffffffffu, v, o);
        if (lane >= o) v += t;
    }
    __shared__ unsigned wtot[8];
    if (lane == 31) wtot[wp] = v;
    __syncthreads();
    unsigned wo = 0;
    for (int w = 0; w < wp; w++) wo += wtot[w];
    unsigned excl = wo + v - s;
    sP[tid] = excl;
    if (tid == 255) sP[256] = excl + s;
    __syncthreads();
}

__device__ __forceinline__ void block_exscan_chunks(const unsigned int* sh,
                                                    unsigned int* sP, int chunk) {
    int tid = threadIdx.x;
    unsigned s = 0;
#pragma unroll 4
    for (int j = 0; j < chunk; j++) s += sh[tid * chunk + j];
    scan256(s, sP);
}

__device__ __forceinline__ int bsearch256(const unsigned int* sP, unsigned rank) {
    int lo = 0, hi = 255;
    while (lo < hi) {
        int mid = (lo + hi + 1) >> 1;
        if (sP[mid] <= rank) lo = mid; else hi = mid - 1;
    }
    return lo;
}

__device__ __forceinline__ void resolve_one(const unsigned int* sh, const unsigned int* sP,
                                            int chunk, int nb, unsigned rank,
                                            unsigned* bin_out, unsigned* rem_out) {
    int lo = bsearch256(sP, rank);
    unsigned cum = sP[lo];
    int bin = lo * chunk;
    int end = bin + chunk;
    if (end > nb) end = nb;
    while (bin + 1 < end && cum + sh[bin] <= rank) { cum += sh[bin]; bin++; }
    *bin_out = (unsigned)bin;
    *rem_out = rank - cum;
}

__device__ __forceinline__ void ranks_for_n(int n, unsigned* r) {
    int nm1 = (n > 1) ? (n - 1) : 0;
    float pos05 = 0.05f * (float)nm1;
    float pos95 = 0.95f * (float)nm1;
    r[0] = (unsigned)floorf(pos05);
    r[1] = (unsigned)ceilf(pos05);
    r[2] = (unsigned)floorf(pos95);
    r[3] = (unsigned)ceilf(pos95);
}

// ---------------- kernels ----------------
// Pass 1: moments + compacted gt keys + smem hist L0 (12-bit) + dp/dgt/m12 precompute.
// Block-aggregated counter reservation. Last block per batch resolves L0 prefixes.
__global__ void k_stats(const float* __restrict__ pred, const float* __restrict__ gt,
                        const float* __restrict__ mask) {
    __shared__ unsigned int hh[NB0];
    __shared__ unsigned int sPP[257];
    __shared__ unsigned swt[8];      // per-warp totals
    __shared__ unsigned swoff[8];    // per-warp offsets
    __shared__ unsigned sbase;
    __shared__ int s_last;
    int b = blockIdx.y;
    int tid = threadIdx.x;
    for (int i = tid; i < NB0; i += blockDim.x) hh[i] = 0u;
    __syncthreads();
    const float4* p0 = (const float4*)(pred + (size_t)b * N2);
    const float4* p1 = (const float4*)(pred + (size_t)b * N2 + NPIX);
    const float4* g0 = (const float4*)(gt   + (size_t)b * N2);
    const float4* g1 = (const float4*)(gt   + (size_t)b * N2 + NPIX);
    const float4* m0 = (const float4*)(mask + (size_t)b * N2);
    const float4* m1 = (const float4*)(mask + (size_t)b * N2 + NPIX);
    float4* dp4  = (float4*)(g_dp  + (size_t)b * NPIX);
    float4* dg4  = (float4*)(g_dgt + (size_t)b * NPIX);
    unsigned char* mm = g_m12 + (size_t)b * NPIX4;
    unsigned int* keys = g_keys + (size_t)b * N2;
    float a00 = 0.f, a01 = 0.f, a11 = 0.f, bb0 = 0.f, bb1 = 0.f;
    int lane = tid & 31;
    int wp = tid >> 5;
    int tot_threads = gridDim.x * blockDim.x;
    for (int i = blockIdx.x * blockDim.x + tid; i < NPIX4; i += tot_threads) {
        float4 P0 = __ldcs(p0 + i), P1 = __ldcs(p1 + i);
        float4 G0 = __ldcs(g0 + i), G1 = __ldcs(g1 + i);
        float4 M0 = __ldcs(m0 + i), M1 = __ldcs(m1 + i);
        float4 dpv, dgv;
        unsigned kv[8];
        unsigned actbits = 0, mbyte = 0;
#define DO(c, idx, bit) { bool a0 = M0.c > 0.5f, a1 = M1.c > 0.5f; \
        if (a0) { a00 += P0.c * P0.c; a01 += P0.c; a11 += 1.f; bb0 += P0.c * G0.c; bb1 += G0.c; } \
        if (a1) { a00 += P1.c * P1.c; a01 += P1.c; a11 += 1.f; bb0 += P1.c * G1.c; bb1 += G1.c; } \
        if (a0) actbits |= (1u << idx); kv[idx] = fkey(G0.c); \
        if (a1) actbits |= (1u << (idx + 4)); kv[idx + 4] = fkey(G1.c); \
        if (a0 && a1) mbyte |= (1u << bit); \
        dpv.c = P1.c - P0.c; dgv.c = G1.c - G0.c; }
        DO(x, 0, 0) DO(y, 1, 1) DO(z, 2, 2) DO(w, 3, 3)
#undef DO
        int tot = __popc(actbits), excl, wtot;
        warp_exscan(tot, lane, &excl, &wtot);
        if (lane == 0) swt[wp] = (unsigned)wtot;
        __syncthreads();
        if (tid == 0) {
            unsigned acc = 0;
            for (int w = 0; w < 8; w++) { swoff[w] = acc; acc += swt[w]; }
            sbase = acc ? (unsigned)atomicAdd(&g_cntm[b], (int)acc) : 0u;
        }
        __syncthreads();
        unsigned pos = sbase + swoff[wp] + (unsigned)excl;
#pragma unroll
        for (int s = 0; s < 8; s++) {
            if (actbits & (1u << s)) {
                keys[pos] = kv[s];
                atomicAdd(&hh[kv[s] >> 20], 1u);
                pos++;
            }
        }
        dp4[i] = dpv; dg4[i] = dgv; mm[i] = (unsigned char)mbyte;
    }
    double d0 = a00, d1 = a01, d2 = a11, d3 = bb0, d4 = bb1;
    for (int off = 16; off > 0; off >>= 1) {
        d0 += __shfl_down_sync(0xffffffffu, d0, off);
        d1 += __shfl_down_sync(0xffffffffu, d1, off);
        d2 += __shfl_down_sync(0xffffffffu, d2, off);
        d3 += __shfl_down_sync(0xffffffffu, d3, off);
        d4 += __shfl_down_sync(0xffffffffu, d4, off);
    }
    __shared__ double shd[8][5];
    if (lane == 0) { shd[wp][0] = d0; shd[wp][1] = d1; shd[wp][2] = d2; shd[wp][3] = d3; shd[wp][4] = d4; }
    __syncthreads();
    if (tid == 0) {
        double s0 = 0, s1 = 0, s2 = 0, s3 = 0, s4 = 0;
        for (int w = 0; w < 8; w++) { s0 += shd[w][0]; s1 += shd[w][1]; s2 += shd[w][2]; s3 += shd[w][3]; s4 += shd[w][4]; }
        atomicAdd(&g_sums[b][0], s0); atomicAdd(&g_sums[b][1], s1);
        atomicAdd(&g_sums[b][2], s2); atomicAdd(&g_sums[b][3], s3);
        atomicAdd(&g_sums[b][4], s4);
    }
    unsigned int* gh = g_hist0[b];
    for (int i = tid; i < NB0; i += blockDim.x) {
        unsigned v = hh[i];
        if (v) atomicAdd(&gh[i], v);
    }
    // ---- fused resolveA: last block of this batch resolves L0 prefixes ----
    __threadfence();
    __syncthreads();
    if (tid == 0) s_last = (atomicAdd(&g_arrive[b], 1) == (int)gridDim.x - 1) ? 1 : 0;
    __syncthreads();
    if (s_last) {
        __threadfence();
        int n = g_cntm[b];
        for (int i = tid; i < NB0; i += blockDim.x) hh[i] = g_hist0[b][i];
        __syncthreads();
        block_exscan_chunks(hh, sPP, NB0 / 256);
        if (tid < 4) {
            unsigned rk[4]; ranks_for_n(n, rk);
            unsigned bin = 0, rem = 0;
            if (n > 0) resolve_one(hh, sPP, NB0 / 256, NB0, rk[tid], &bin, &rem);
            g_pref[b * 4 + tid] = bin;
            g_rem[b * 4 + tid] = rem;
        }
        for (int i = tid; i < NB0; i += blockDim.x) g_hist0[b][i] = 0u;  // replay-safe
        if (tid == 0) g_arrive[b] = 0;
    }
}

// One pass over compacted keys: smem-staged candidate gather.
__global__ void k_gather() {
    __shared__ unsigned buf[4][LCAP];
    __shared__ int lcnt[4];
    __shared__ int gbase[4];
    __shared__ unsigned spref[4];
    int b = blockIdx.y, tid = threadIdx.x;
    if (tid < 4) { lcnt[tid] = 0; spref[tid] = g_pref[b * 4 + tid]; }
    __syncthreads();
    int n = g_cntm[b];
    unsigned p0 = spref[0], p1 = spref[1], p2 = spref[2], p3 = spref[3];
    const unsigned int* keys = g_keys + (size_t)b * N2;
    const uint4* k4 = (const uint4*)keys;
    int n4 = n >> 2;
    int stride = gridDim.x * blockDim.x;
#define TRY(key, q) { int p = atomicAdd(&lcnt[q], 1); \
        if (p < LCAP) buf[q][p] = (key); \
        else { int g = atomicAdd(&g_candcnt[b * 4 + q], 1); \
               if (g < CAP) g_cand[(b * 4 + q) * CAP + g] = (key); } }
#define PROC(key) { unsigned hi = (key) >> 20; \
        if (hi == p0) TRY(key, 0) \
        if (hi == p1) TRY(key, 1) \
        if (hi == p2) TRY(key, 2) \
        if (hi == p3) TRY(key, 3) }
    for (int i = blockIdx.x * blockDim.x + tid; i < n4; i += stride) {
        uint4 kk = __ldcs(k4 + i);
        PROC(kk.x) PROC(kk.y) PROC(kk.z) PROC(kk.w)
    }
    if (blockIdx.x == 0) {
        for (int i = (n4 << 2) + tid; i < n; i += blockDim.x) {
            unsigned key = keys[i];
            PROC(key)
        }
    }
#undef PROC
#undef TRY
    __syncthreads();
    if (tid < 4) {
        int c = lcnt[tid]; if (c > LCAP) c = LCAP;
        gbase[tid] = atomicAdd(&g_candcnt[b * 4 + tid], c);
    }
    __syncthreads();
    for (int q = 0; q < 4; q++) {
        int c = lcnt[q]; if (c > LCAP) c = LCAP;
        int base = gbase[q];
        unsigned int* dst = g_cand + (size_t)(b * 4 + q) * CAP;
        for (int i = tid; i < c; i += blockDim.x) {
            int pos = base + i;
            if (pos < CAP) dst[pos] = buf[q][i];
        }
    }
}

// grid=(4,BB): one block per (batch,query). Candidates read once into registers;
// 2048-bin mid hist [9:20) + collect winning bin + counting select -> g_qv.
__global__ void k_resolveB() {
    __shared__ unsigned sh[2048];
    __shared__ unsigned sP[257];
    __shared__ unsigned sbin, srem;
    __shared__ unsigned slist[RBSEL];
    __shared__ int slcnt;
    __shared__ unsigned s_target;
    int q = blockIdx.x, b = blockIdx.y, tid = threadIdx.x;
    int bq = b * 4 + q;
    int n = g_cntm[b];
    if (n == 0) { if (tid == 0) g_qv[bq] = 0.f; return; }
    int cnt = g_candcnt[bq];
    if (cnt > CAP) cnt = CAP;
    unsigned rank = g_rem[bq];
    const unsigned int* gcd = g_cand + (size_t)bq * CAP;
    unsigned kbuf[KREG];
    int nk = 0;
    for (int i = tid; i < cnt && nk < KREG; i += 256) kbuf[nk++] = gcd[i];
    for (int i = tid; i < 2048; i += 256) sh[i] = 0u;
    __syncthreads();
    {
        int kk = 0;
        for (int i = tid; i < cnt; i += 256, kk++) {
            unsigned key = (kk < KREG) ? kbuf[kk] : gcd[i];
            atomicAdd(&sh[(key >> 9) & 2047u], 1u);
        }
    }
    __syncthreads();
    block_exscan_chunks(sh, sP, 8);
    if (tid == 0) {
        unsigned bin, rem;
        resolve_one(sh, sP, 8, 2048, rank, &bin, &rem);
        sbin = bin; srem = rem;
        slcnt = 0;
    }
    __syncthreads();
    unsigned binM = sbin, remM = srem;
    // collect the winning-bin keys (expected ~2-4)
    {
        int kk = 0;
        for (int i = tid; i < cnt; i += 256, kk++) {
            unsigned key = (kk < KREG) ? kbuf[kk] : gcd[i];
            if (((key >> 9) & 2047u) == binM) {
                int p = atomicAdd(&slcnt, 1);
                if (p < RBSEL) slist[p] = key;
            }
        }
    }
    __syncthreads();
    int m = slcnt;
    if (m <= RBSEL) {
        // tie-aware counting select among m keys
        for (int i = tid; i < m; i += 256) {
            unsigned x = slist[i];
            unsigned cl = 0, ce = 0;
            for (int jj = 0; jj < m; jj++) {
                unsigned y = slist[jj];
                cl += (y < x); ce += (y == x);
            }
            if (cl <= remM && remM < cl + ce) s_target = x;   // all writers agree
        }
        __syncthreads();
        if (tid == 0) g_qv[bq] = kinv(s_target);
    } else {
        // fallback: 512-bin low hist (bits [0:9)) + scan resolve
        for (int i = tid; i < 512; i += 256) sh[i] = 0u;
        __syncthreads();
        int kk = 0;
        for (int i = tid; i < cnt; i += 256, kk++) {
            unsigned key = (kk < KREG) ? kbuf[kk] : gcd[i];
            if (((key >> 9) & 2047u) == binM) atomicAdd(&sh[key & 511u], 1u);
        }
        __syncthreads();
        block_exscan_chunks(sh, sP, 2);
        if (tid == 0) {
            unsigned bin, rem;
            resolve_one(sh, sP, 2, 512, remM, &bin, &rem);
            unsigned full = (g_pref[bq] << 20) | (binM << 9) | bin;
            g_qv[bq] = kinv(full);
        }
    }
}

// curr_grad output + static residual compaction + trim L0 hist build.
// Block-aggregated g_cnt reservation. Thread-0 prelude computes scalars.
__global__ void k_compact(const float* __restrict__ prev, float* __restrict__ out) {
    __shared__ float sh_s, sh_th, sh_sc;
    __shared__ unsigned swt[8], swoff[8], sbase;
    int b = blockIdx.y, tid = threadIdx.x;
    if (tid == 0) {
        double a00 = g_sums[b][0], a01 = g_sums[b][1], a11 = g_sums[b][2];
        double bb0 = g_sums[b][3], bb1 = g_sums[b][4];
        double det = a00 * a11 - a01 * a01;
        float s = 0.f;
        if (det != 0.0) {
            double id = 1.0 / (det + 1e-6);
            s = (float)((a11 * bb0 - a01 * bb1) * id);
        }
        int n = g_cntm[b];
        float rr = 1.0f;
        if (n > 0) {
            float v0 = g_qv[b * 4 + 0], v1 = g_qv[b * 4 + 1];
            float v2 = g_qv[b * 4 + 2], v3 = g_qv[b * 4 + 3];
            int nm1 = (n > 1) ? (n - 1) : 0;
            float pos05 = 0.05f * (float)nm1, pos95 = 0.95f * (float)nm1;
            float lo = v0 + (v1 - v0) * (pos05 - floorf(pos05));
            float hi = v2 + (v3 - v2) * (pos95 - floorf(pos95));
            bool valid = isfinite(lo) && isfinite(hi) && (hi - lo > 0.f) &&
                         (fabsf(lo) < 1e30f) && (fabsf(hi) < 1e30f);
            rr = valid ? fmaxf(hi - lo, 1e-6f) : 1.0f;
        }
        sh_s = s; sh_sc = fmaxf(rr, 1e-6f); sh_th = 0.01f * rr;
        if (blockIdx.x == 0) g_rr[b] = rr;
    }
    __syncthreads();
    float s = sh_s, th = sh_th, sc = sh_sc;
    const float4* dp4 = (const float4*)(g_dp  + (size_t)b * NPIX);
    const float4* dg4 = (const float4*)(g_dgt + (size_t)b * NPIX);
    const float4* pv4 = (const float4*)(prev + (size_t)b * NPIX);
    const unsigned char* mm = g_m12 + (size_t)b * NPIX4;
    float4* o4 = (float4*)(out + 4 + (size_t)b * NPIX);
    int lane = tid & 31;
    int wp = tid >> 5;
    int tot_threads = gridDim.x * blockDim.x;
    for (int i = blockIdx.x * blockDim.x + tid; i < NPIX4; i += tot_threads) {
        float4 DP = __ldcs(dp4 + i), DG = __ldcs(dg4 + i), PV = __ldcs(pv4 + i);
        unsigned mbyte = __ldcs(mm + i);
        float4 O;
        unsigned actbits = 0;
        float rdv[4], rav[4];
#define DO(c, idx) { float dp = s * DP.c; O.c = dp; \
        bool st = ((mbyte >> idx) & 1u) && (fabsf(DG.c) < th); \
        if (st) actbits |= (1u << idx); \
        rdv[idx] = fabsf(dp - DG.c) / sc; rav[idx] = fabsf(dp - PV.c) / sc; }
        DO(x, 0) DO(y, 1) DO(z, 2) DO(w, 3)
#undef DO
        __stcs(o4 + i, O);
        int tot = __popc(actbits), excl, wtot;
        warp_exscan(tot, lane, &excl, &wtot);
        if (lane == 0) swt[wp] = (unsigned)wtot;
        __syncthreads();
        if (tid == 0) {
            unsigned acc = 0;
            for (int w = 0; w < 8; w++) { swoff[w] = acc; acc += swt[w]; }
            sbase = acc ? (unsigned)atomicAdd(&g_cnt[b], (int)acc) : 0u;
        }
        __syncthreads();
        if (actbits) {
            unsigned pos = sbase + swoff[wp] + (unsigned)excl;
#pragma unroll
            for (int q = 0; q < 4; q++) {
                if (actbits & (1u << q)) {
                    unsigned kd = fkey(rdv[q]), ka = fkey(rav[q]);
                    g_rd_keys[(size_t)b * NPIX + pos] = kd;
                    g_ra_keys[(size_t)b * NPIX + pos] = ka;
                    atomicAdd(&g_histt[b * 2 + 0][kd >> 21], 1u);
                    atomicAdd(&g_histt[b * 2 + 1][ka >> 21], 1u);
                    pos++;
                }
            }
        }
    }
}

// Trimmed-huber: per (batch, j) block. L0 from precomputed g_histt, then
// collect winning-bin keys and do an exact tie-aware counting select
// (one radix fallback level if the bin is large). Last block reduces + re-zeroes.
__global__ void k_trim(float* __restrict__ out) {
    __shared__ unsigned int skeys[8192];
    __shared__ unsigned int slist[8192];
    __shared__ unsigned int sh[2048];
    __shared__ unsigned int sP[257];
    __shared__ unsigned int s_target;
    __shared__ int slcnt, sl2cnt;
    __shared__ unsigned sbin, srem;
    __shared__ int s_last;
    int tid = threadIdx.x;
    int b = blockIdx.y, j = blockIdx.x;
    int bj = b * 2 + j;
    const unsigned int* gkeys = (j ? g_ra_keys : g_rd_keys) + (size_t)b * NPIX;
    int cnt = g_cnt[b];
    int k = (int)floorf(0.6f * (float)cnt);
    if (k > 0) {
        bool insm = (cnt <= 8192);
        if (insm) for (int i = tid; i < cnt; i += 256) skeys[i] = gkeys[i];
        const unsigned int* keys = insm ? skeys : gkeys;
        for (int i = tid; i < 2048; i += 256) sh[i] = g_histt[bj][i];
        __syncthreads();
        block_exscan_chunks(sh, sP, 8);
        if (tid == 0) {
            unsigned bin, rem;
            resolve_one(sh, sP, 8, 2048, (unsigned)(k - 1), &bin, &rem);
            sbin = bin; srem = rem;
            slcnt = 0;
        }
        __syncthreads();
        unsigned bin0 = sbin;
        for (int i = tid; i < cnt; i += 256) {
            unsigned key = keys[i];
            if ((key >> 21) == bin0) {
                int p = atomicAdd(&slcnt, 1);
                if (p < 8192) slist[p] = key;
            }
        }
        __syncthreads();
        int m = slcnt; if (m > 8192) m = 8192;
        unsigned r = srem;
        if (m <= SELTH) {
            for (int i = tid; i < m; i += 256) {
                unsigned x = slist[i];
                unsigned cl = 0, ce = 0;
                for (int jj = 0; jj < m; jj++) {
                    unsigned y = slist[jj];
                    cl += (y < x); ce += (y == x);
                }
                if (cl <= r && r < cl + ce) s_target = x;
            }
            __syncthreads();
        } else {
            for (int i = tid; i < 2048; i += 256) sh[i] = 0u;
            __syncthreads();
            for (int i = tid; i < m; i += 256) atomicAdd(&sh[(slist[i] >> 10) & 2047u], 1u);
            __syncthreads();
            block_exscan_chunks(sh, sP, 8);
            if (tid == 0) {
                unsigned bin, rem;
                resolve_one(sh, sP, 8, 2048, r, &bin, &rem);
                sbin = bin; srem = rem;
                sl2cnt = 0;
            }
            __syncthreads();
            unsigned bin1 = sbin;
            for (int i = tid; i < m; i += 256) {
                unsigned key = slist[i];
                if (((key >> 10) & 2047u) == bin1) {
                    int p = atomicAdd(&sl2cnt, 1);
                    if (p < 2048) sh[p] = key;
                }
            }
            __syncthreads();
            int m2 = sl2cnt; if (m2 > 2048) m2 = 2048;
            unsigned r2 = srem;
            for (int i = tid; i < m2; i += 256) {
                unsigned x = sh[i];
                unsigned cl = 0, ce = 0;
                for (int jj = 0; jj < m2; jj++) {
                    unsigned y = sh[jj];
                    cl += (y < x); ce += (y == x);
                }
                if (cl <= r2 && r2 < cl + ce) s_target = x;
            }
            __syncthreads();
        }
        unsigned target = s_target;
        float sum = 0.f;
        unsigned less = 0;
        for (int i = tid; i < cnt; i += 256) {
            unsigned key = keys[i];
            if (key < target) { sum += hubf(kinv(key)); less++; }
        }
        for (int o = 16; o > 0; o >>= 1) {
            sum  += __shfl_down_sync(0xffffffffu, sum, o);
            less += __shfl_down_sync(0xffffffffu, less, o);
        }
        __shared__ float ss[8];
        __shared__ unsigned sl[8];
        int lane = tid & 31, wp = tid >> 5;
        if (lane == 0) { ss[wp] = sum; sl[wp] = less; }
        __syncthreads();
        if (tid == 0) {
            float S = 0.f; unsigned L = 0;
            for (int w = 0; w < 8; w++) { S += ss[w]; L += sl[w]; }
            float ht = hubf(kinv(target));
            g_loss[bj] = (S + (float)(k - (int)L) * ht) / (float)k;
        }
    } else {
        if (tid == 0) g_loss[bj] = 0.f;
    }
    for (int i = tid; i < 2048; i += 256) g_histt[bj][i] = 0u;   // replay-safe
    __threadfence();
    __syncthreads();
    if (tid == 0) s_last = (atomicAdd(&g_done, 1) == 31) ? 1 : 0;
    __syncthreads();
    if (s_last) {
        __threadfence();
        if (tid < BB) {
            for (int jj = 0; jj < 5; jj++) g_sums[tid][jj] = 0.0;
            g_cntm[tid] = 0;
            g_cnt[tid] = 0;
            for (int q = 0; q < 4; q++) g_candcnt[tid * 4 + q] = 0;
        }
        if (tid == 0) {
            float sld = 0.f, sla = 0.f, srr = 0.f;
            for (int i = 0; i < BB; i++) {
                sld += g_loss[i * 2];
                sla += g_loss[i * 2 + 1];
                srr += g_rr[i];
            }
            float loss_data = sld / (float)BB;
            float loss_acc  = sla / (float)BB;
            out[0] = loss_data + 0.2f * loss_acc;
            out[1] = loss_data;
            out[2] = loss_acc;
            out[3] = srr / (float)BB;
            g_done = 0;   // replay-safe
        }
    }
}

extern "C" void kernel_launch(void* const* d_in, const int* in_sizes, int n_in,
                              void* d_out, int out_size) {
    const float* pred = (const float*)d_in[0];
    const float* gt   = (const float*)d_in[1];
    const float* mask = (const float*)d_in[2];
    const float* prev = (const float*)d_in[3];
    float* out = (float*)d_out;
    dim3 big(60, BB);

    k_stats<<<big, 256>>>(pred, gt, mask);     // + fused resolveA tail
    k_gather<<<big, 256>>>();
    k_resolveB<<<dim3(4, BB), 256>>>();
    k_compact<<<big, 256>>>(prev, out);
    k_trim<<<dim3(2, BB), 256>>>(out);         // + fused final reduction
}